// round 2
// baseline (speedup 1.0000x reference)
#include <cuda_runtime.h>

// ---------------------------------------------------------------------------
// BenesBlock: 25 switch-unit steps on [8192, 512] fp32.
// Per step: v=[4096,1024]; h = v@w1 [4096,2048]; per-COLUMN (axis-0) LN;
// leaky_relu(0.2); cand = h@w2 + b2 -> [8192,512];
// y = sigmoid(rs)*x + cand*CW; then closed-form shuffle permutation.
// Steps 0-11: weights f, scatter dst=ROL[j]; 12-23: weights r, scatter ROR[j];
// step 24: weights m, no permutation, writes d_out.
// ---------------------------------------------------------------------------

#define L    8192
#define NU   512
#define M_   4096      // L/2
#define K1   1024      // 2*NU
#define N1   2048      // 4*NU
#define K2   2048
#define N2   1024
#define CW_F 0.10897247358851683f   // sqrt(1-0.9^2)*0.25
#define EPS_F 1e-6f

#define BM 128
#define BN 128
#define BK 16
#define TM 8
#define TN 8

// Scratch (static device globals — no allocation allowed).
__device__ float g_y[2][L * NU];          // ping-pong activations (2 x 16MB)
__device__ float g_h[M_ * N1];            // GEMM1 output (32MB)
__device__ float g_part[8][2 * N1];       // deterministic partial col sums
__device__ float g_stats[2 * N1];         // (mean, rstd) interleaved per column
__device__ float g_sig[3 * NU];           // sigmoid(rs) for f/r/m

// ---------------------------------------------------------------------------
__global__ void copy_x_kernel(const float* __restrict__ x) {
    int i = blockIdx.x * blockDim.x + threadIdx.x;   // float4 index
    const float4* src = (const float4*)x;
    float4* dst = (float4*)g_y[0];
    if (i < (L * NU) / 4) dst[i] = src[i];
}

__global__ void sig_kernel(const float* __restrict__ rs_f,
                           const float* __restrict__ rs_r,
                           const float* __restrict__ rs_m) {
    int i = blockIdx.x * blockDim.x + threadIdx.x;
    if (i >= 3 * NU) return;
    const float* src = (i < NU) ? rs_f : (i < 2 * NU) ? rs_r : rs_m;
    float v = src[i & (NU - 1)];
    g_sig[i] = 1.0f / (1.0f + expf(-v));
}

// ---------------------------------------------------------------------------
// GEMM1: h = v @ w1.  A = g_y[cur] viewed [4096,1024], B = w1 [1024,2048].
__global__ __launch_bounds__(256) void gemm1_kernel(int cur, const float* __restrict__ w1) {
    __shared__ float As[BK][BM + 4];
    __shared__ float Bs[BK][BN];
    const float* __restrict__ A = g_y[cur];

    const int tid = threadIdx.x;
    const int tx = tid & 15, ty = tid >> 4;
    const int m0 = blockIdx.y * BM, n0 = blockIdx.x * BN;

    const int aRow = tid >> 2;          // 0..63
    const int aCol = (tid & 3) * 4;     // 0,4,8,12
    const int bRow = tid >> 5;          // 0..7
    const int bCol = (tid & 31) * 4;

    float acc[TM][TN];
#pragma unroll
    for (int i = 0; i < TM; i++)
#pragma unroll
        for (int j = 0; j < TN; j++) acc[i][j] = 0.f;

    for (int k0 = 0; k0 < K1; k0 += BK) {
#pragma unroll
        for (int p = 0; p < 2; p++) {
            int m = aRow + p * 64;
            float4 v = *(const float4*)&A[(size_t)(m0 + m) * K1 + k0 + aCol];
            As[aCol + 0][m] = v.x; As[aCol + 1][m] = v.y;
            As[aCol + 2][m] = v.z; As[aCol + 3][m] = v.w;
        }
#pragma unroll
        for (int p = 0; p < 2; p++) {
            int kk = bRow + p * 8;
            *(float4*)&Bs[kk][bCol] =
                *(const float4*)&w1[(size_t)(k0 + kk) * N1 + n0 + bCol];
        }
        __syncthreads();
#pragma unroll
        for (int kk = 0; kk < BK; kk++) {
            float a[TM], b[TN];
#pragma unroll
            for (int i = 0; i < TM; i++) a[i] = As[kk][ty * TM + i];
#pragma unroll
            for (int j = 0; j < TN; j++) b[j] = Bs[kk][tx * TN + j];
#pragma unroll
            for (int i = 0; i < TM; i++)
#pragma unroll
                for (int j = 0; j < TN; j++) acc[i][j] = fmaf(a[i], b[j], acc[i][j]);
        }
        __syncthreads();
    }
#pragma unroll
    for (int i = 0; i < TM; i++) {
        int r = m0 + ty * TM + i;
#pragma unroll
        for (int j = 0; j < TN; j += 4) {
            float4 v = make_float4(acc[i][j], acc[i][j + 1], acc[i][j + 2], acc[i][j + 3]);
            *(float4*)&g_h[(size_t)r * N1 + n0 + tx * TN + j] = v;
        }
    }
}

// ---------------------------------------------------------------------------
// Column stats of h over 4096 rows (deterministic, two-stage, no atomics).
__global__ void stats_partial_kernel() {   // grid (64, 8), block (32, 8)
    int col = blockIdx.x * 32 + threadIdx.x;
    int rg = blockIdx.y;
    float s = 0.f, q = 0.f;
    for (int r = rg * 512 + threadIdx.y; r < (rg + 1) * 512; r += 8) {
        float v = g_h[(size_t)r * N1 + col];
        s += v; q += v * v;
    }
    __shared__ float sh[2][8][32];
    sh[0][threadIdx.y][threadIdx.x] = s;
    sh[1][threadIdx.y][threadIdx.x] = q;
    __syncthreads();
    if (threadIdx.y == 0) {
        float S = 0.f, Q = 0.f;
#pragma unroll
        for (int t = 0; t < 8; t++) { S += sh[0][t][threadIdx.x]; Q += sh[1][t][threadIdx.x]; }
        g_part[rg][2 * col] = S;
        g_part[rg][2 * col + 1] = Q;
    }
}

__global__ void stats_final_kernel() {     // grid 8, block 256
    int c = blockIdx.x * 256 + threadIdx.x;
    if (c >= N1) return;
    float s = 0.f, q = 0.f;
#pragma unroll
    for (int rg = 0; rg < 8; rg++) { s += g_part[rg][2 * c]; q += g_part[rg][2 * c + 1]; }
    float mean = s * (1.0f / M_);
    float var = q * (1.0f / M_) - mean * mean;     // E[(h-mean)^2]
    g_stats[2 * c] = mean;
    g_stats[2 * c + 1] = rsqrtf(var + EPS_F);
}

// ---------------------------------------------------------------------------
// GEMM2: cand = lrelu(LN(h)) @ w2 + b2, fused residual + permutation scatter.
// dir: 0 = scatter ROL (forward), 1 = scatter ROR (reverse), 2 = identity.
__global__ __launch_bounds__(256) void gemm2_kernel(const float* __restrict__ w2,
                                                    const float* __restrict__ b2,
                                                    int stage, int dir, int cur,
                                                    float* __restrict__ dext) {
    __shared__ float As[BK][BM + 4];
    __shared__ float Bs[BK][BN];

    const int tid = threadIdx.x;
    const int tx = tid & 15, ty = tid >> 4;
    const int m0 = blockIdx.y * BM, n0 = blockIdx.x * BN;

    const int aRow = tid >> 2;
    const int aCol = (tid & 3) * 4;
    const int bRow = tid >> 5;
    const int bCol = (tid & 31) * 4;

    float acc[TM][TN];
#pragma unroll
    for (int i = 0; i < TM; i++)
#pragma unroll
        for (int j = 0; j < TN; j++) acc[i][j] = 0.f;

    for (int k0 = 0; k0 < K2; k0 += BK) {
        int kg = k0 + aCol;
        float4 sa = *(const float4*)&g_stats[2 * kg];       // mean k, rstd k, mean k+1, rstd k+1
        float4 sb = *(const float4*)&g_stats[2 * kg + 4];
#pragma unroll
        for (int p = 0; p < 2; p++) {
            int m = aRow + p * 64;
            float4 v = *(const float4*)&g_h[(size_t)(m0 + m) * K2 + kg];
            v.x = (v.x - sa.x) * sa.y;
            v.y = (v.y - sa.z) * sa.w;
            v.z = (v.z - sb.x) * sb.y;
            v.w = (v.w - sb.z) * sb.w;
            v.x = v.x > 0.f ? v.x : 0.2f * v.x;
            v.y = v.y > 0.f ? v.y : 0.2f * v.y;
            v.z = v.z > 0.f ? v.z : 0.2f * v.z;
            v.w = v.w > 0.f ? v.w : 0.2f * v.w;
            As[aCol + 0][m] = v.x; As[aCol + 1][m] = v.y;
            As[aCol + 2][m] = v.z; As[aCol + 3][m] = v.w;
        }
#pragma unroll
        for (int p = 0; p < 2; p++) {
            int kk = bRow + p * 8;
            *(float4*)&Bs[kk][bCol] =
                *(const float4*)&w2[(size_t)(k0 + kk) * N2 + n0 + bCol];
        }
        __syncthreads();
#pragma unroll
        for (int kk = 0; kk < BK; kk++) {
            float a[TM], b[TN];
#pragma unroll
            for (int i = 0; i < TM; i++) a[i] = As[kk][ty * TM + i];
#pragma unroll
            for (int j = 0; j < TN; j++) b[j] = Bs[kk][tx * TN + j];
#pragma unroll
            for (int i = 0; i < TM; i++)
#pragma unroll
                for (int j = 0; j < TN; j++) acc[i][j] = fmaf(a[i], b[j], acc[i][j]);
        }
        __syncthreads();
    }

    float* yout = dext ? dext : g_y[cur ^ 1];
    const float* ycur = g_y[cur];
#pragma unroll
    for (int i = 0; i < TM; i++) {
        int r = m0 + ty * TM + i;
#pragma unroll
        for (int j = 0; j < TN; j++) {
            int n = n0 + tx * TN + j;
            float cand = acc[i][j] + b2[n];
            int c = n & (NU - 1);
            int rowY = 2 * r + (n >> 9);
            float val = g_sig[stage * NU + c] * ycur[(size_t)r * 1024 + n] + cand * CW_F;
            int dst;
            if (dir == 0)       dst = (rowY < M_) ? (2 * rowY) : (2 * rowY - L + 1);
            else if (dir == 1)  dst = (rowY & 1) ? (M_ + (rowY >> 1)) : (rowY >> 1);
            else                dst = rowY;
            yout[(size_t)dst * NU + c] = val;
        }
    }
}

// ---------------------------------------------------------------------------
extern "C" void kernel_launch(void* const* d_in, const int* in_sizes, int n_in,
                              void* d_out, int out_size) {
    const float* x = (const float*)d_in[0];
    const float* rs[3] = {(const float*)d_in[1], (const float*)d_in[5], (const float*)d_in[9]};
    const float* w1[3] = {(const float*)d_in[2], (const float*)d_in[6], (const float*)d_in[10]};
    const float* w2[3] = {(const float*)d_in[3], (const float*)d_in[7], (const float*)d_in[11]};
    const float* b2[3] = {(const float*)d_in[4], (const float*)d_in[8], (const float*)d_in[12]};
    float* out = (float*)d_out;

    copy_x_kernel<<<(L * NU / 4 + 255) / 256, 256>>>(x);
    sig_kernel<<<6, 256>>>(rs[0], rs[1], rs[2]);

    dim3 blk(256);
    dim3 g1(N1 / BN, M_ / BM);   // (16, 32)
    dim3 g2(N2 / BN, M_ / BM);   // (8, 32)

    int cur = 0;
    for (int step = 0; step < 25; step++) {
        int stage = (step < 12) ? 0 : (step < 24) ? 1 : 2;
        int dir = stage;  // 0: scatter ROL, 1: scatter ROR, 2: identity
        gemm1_kernel<<<g1, blk>>>(cur, w1[stage]);
        stats_partial_kernel<<<dim3(64, 8), dim3(32, 8)>>>();
        stats_final_kernel<<<8, 256>>>();
        gemm2_kernel<<<g2, blk>>>(w2[stage], b2[stage], stage, dir, cur,
                                  (step == 24) ? out : nullptr);
        cur ^= 1;
    }
}

// round 4
// speedup vs baseline: 1.9356x; 1.9356x over previous
#include <cuda_runtime.h>
#include <cuda_fp16.h>
#include <cstdint>

// ---------------------------------------------------------------------------
// BenesBlock via mma.sync (HMMA) — tcgen05 is sm_103a-gated and the harness
// ptxas targets plain sm_103, so we use the non-gated tensor-core path.
// fp32 accuracy via fp16 hi/lo split: D += Ah*Bh + Ah*Bl + Al*Bh (fp32 accum).
// ---------------------------------------------------------------------------

#define L    8192
#define NU   512
#define M_   4096
#define K1   1024
#define N1   2048
#define K2   2048
#define N2   1024
#define CW_F 0.10897247358851683f
#define EPS_F 1e-6f

// GEMM tile: BM=128, BN=128, K-chunk = 64 halves (128B rows, SW128 swizzle).
#define STAGE 65536                 // Ah16K | Al16K | Bh16K | Bl16K
#define SMEM_DYN (2 * STAGE)        // double buffered

// ---------------------------------------------------------------------------
// Device globals (no allocation allowed).
__device__ __align__(16) __half g_y16[2][2][L * NU];      // [buf][hi/lo]
__device__ __align__(16) float  g_h[M_ * N1];
__device__ __align__(16) __half g_h2[2][M_ * N1];         // [hi/lo] LN'd
__device__ __align__(16) __half g_w1t[3][2][N1 * K1];     // [stage][hi/lo][N,K]
__device__ __align__(16) __half g_w2t[3][2][N2 * K2];     // [stage][hi/lo][N,K]
__device__ float g_part[8][2 * N1];
__device__ float g_stats[2 * N1];
__device__ float g_sig[3 * NU];

// ---------------------------------------------------------------------------
__device__ __forceinline__ uint32_t smem_u32(const void* p) {
    uint32_t a;
    asm("{ .reg .u64 t; cvta.to.shared.u64 t, %1; cvt.u32.u64 %0, t; }" : "=r"(a) : "l"(p));
    return a;
}
__device__ __forceinline__ uint32_t sw128(uint32_t off) { return off ^ ((off >> 3) & 0x70); }

#define CP16(s, g) asm volatile("cp.async.cg.shared.global [%0], [%1], 16;" :: "r"(s), "l"(g))
#define CP_COMMIT() asm volatile("cp.async.commit_group;" ::: "memory")

#define LDSM4(r0, r1, r2, r3, addr)                                              \
    asm volatile("ldmatrix.sync.aligned.m8n8.x4.shared.b16 {%0,%1,%2,%3}, [%4];" \
                 : "=r"(r0), "=r"(r1), "=r"(r2), "=r"(r3) : "r"(addr))

#define MMA(acc, a, b0, b1)                                                      \
    asm volatile("mma.sync.aligned.m16n8k16.row.col.f32.f16.f16.f32 "            \
                 "{%0,%1,%2,%3}, {%4,%5,%6,%7}, {%8,%9}, {%0,%1,%2,%3};"         \
                 : "+f"((acc)[0]), "+f"((acc)[1]), "+f"((acc)[2]), "+f"((acc)[3])\
                 : "r"((a)[0]), "r"((a)[1]), "r"((a)[2]), "r"((a)[3]),           \
                   "r"(b0), "r"(b1))

__device__ __forceinline__ void split_h(float v, __half& h, __half& l) {
    h = __float2half_rn(v);
    l = __float2half_rn(v - __half2float(h));
}

// ---------------------------------------------------------------------------
// Prep kernels
__global__ void copy_x_split_kernel(const float* __restrict__ x) {
    int i = blockIdx.x * blockDim.x + threadIdx.x;
    if (i >= L * NU) return;
    __half h, l;
    split_h(x[i], h, l);
    g_y16[0][0][i] = h;
    g_y16[0][1][i] = l;
}

__global__ void sig_kernel(const float* __restrict__ rs_f,
                           const float* __restrict__ rs_r,
                           const float* __restrict__ rs_m) {
    int i = blockIdx.x * blockDim.x + threadIdx.x;
    if (i >= 3 * NU) return;
    const float* src = (i < NU) ? rs_f : (i < 2 * NU) ? rs_r : rs_m;
    float v = src[i & (NU - 1)];
    g_sig[i] = 1.0f / (1.0f + expf(-v));
}

// in [R,C] fp32 -> out [C,R] fp16 hi/lo. which: 0 -> w1t, 1 -> w2t.
__global__ void transpose_split_kernel(const float* __restrict__ w, int R, int C,
                                       int which, int stage) {
    __shared__ float t[32][33];
    __half* oh = which ? g_w2t[stage][0] : g_w1t[stage][0];
    __half* ol = which ? g_w2t[stage][1] : g_w1t[stage][1];
    int c0 = blockIdx.x * 32, r0 = blockIdx.y * 32;
    for (int j = threadIdx.y; j < 32; j += 8)
        t[j][threadIdx.x] = w[(size_t)(r0 + j) * C + c0 + threadIdx.x];
    __syncthreads();
    for (int j = threadIdx.y; j < 32; j += 8) {
        float v = t[threadIdx.x][j];           // element (r0+tx, c0+j)
        __half h, l;
        split_h(v, h, l);
        size_t o = (size_t)(c0 + j) * R + r0 + threadIdx.x;
        oh[o] = h;
        ol[o] = l;
    }
}

// ---------------------------------------------------------------------------
// Column stats of h over 4096 rows (deterministic, no atomics).
__global__ void stats_partial_kernel() {   // grid (64, 8), block (32, 8)
    int col = blockIdx.x * 32 + threadIdx.x;
    int rg = blockIdx.y;
    float s = 0.f, q = 0.f;
    for (int r = rg * 512 + threadIdx.y; r < (rg + 1) * 512; r += 8) {
        float v = g_h[(size_t)r * N1 + col];
        s += v; q += v * v;
    }
    __shared__ float sh[2][8][32];
    sh[0][threadIdx.y][threadIdx.x] = s;
    sh[1][threadIdx.y][threadIdx.x] = q;
    __syncthreads();
    if (threadIdx.y == 0) {
        float S = 0.f, Q = 0.f;
#pragma unroll
        for (int t = 0; t < 8; t++) { S += sh[0][t][threadIdx.x]; Q += sh[1][t][threadIdx.x]; }
        g_part[rg][2 * col] = S;
        g_part[rg][2 * col + 1] = Q;
    }
}

__global__ void stats_final_kernel() {     // grid 8, block 256
    int c = blockIdx.x * 256 + threadIdx.x;
    if (c >= N1) return;
    float s = 0.f, q = 0.f;
#pragma unroll
    for (int rg = 0; rg < 8; rg++) { s += g_part[rg][2 * c]; q += g_part[rg][2 * c + 1]; }
    float mean = s * (1.0f / M_);
    float var = q * (1.0f / M_) - mean * mean;
    g_stats[2 * c] = mean;
    g_stats[2 * c + 1] = rsqrtf(var + EPS_F);
}

// LN + leaky-relu + fp16 split: g_h -> g_h2[hi/lo]
__global__ void prep2_kernel() {           // grid 8192, block 256 (float4/thread)
    int i4 = blockIdx.x * 256 + threadIdx.x;
    float4 v = ((const float4*)g_h)[i4];
    int col = (i4 * 4) & (N1 - 1);
    float4 sa = *(const float4*)&g_stats[2 * col];
    float4 sb = *(const float4*)&g_stats[2 * col + 4];
    float e0 = (v.x - sa.x) * sa.y, e1 = (v.y - sa.z) * sa.w;
    float e2 = (v.z - sb.x) * sb.y, e3 = (v.w - sb.z) * sb.w;
    e0 = e0 > 0.f ? e0 : 0.2f * e0;
    e1 = e1 > 0.f ? e1 : 0.2f * e1;
    e2 = e2 > 0.f ? e2 : 0.2f * e2;
    e3 = e3 > 0.f ? e3 : 0.2f * e3;
    __half h0, l0, h1, l1, h2, l2, h3, l3;
    split_h(e0, h0, l0); split_h(e1, h1, l1);
    split_h(e2, h2, l2); split_h(e3, h3, l3);
    ushort4 ph = make_ushort4(__half_as_ushort(h0), __half_as_ushort(h1),
                              __half_as_ushort(h2), __half_as_ushort(h3));
    ushort4 pl = make_ushort4(__half_as_ushort(l0), __half_as_ushort(l1),
                              __half_as_ushort(l2), __half_as_ushort(l3));
    ((ushort4*)g_h2[0])[i4] = ph;
    ((ushort4*)g_h2[1])[i4] = pl;
}

// ---------------------------------------------------------------------------
// GEMM mainloop: 256 threads, tile 128x128, K-chunks of 64 halves.
// Smem stage: Ah 16K | Al 16K | Bh 16K | Bl 16K, SW128-swizzled 128B rows.
__device__ __forceinline__ void load_stage(uint32_t sb, int s, int ck,
                                           const __half* Ah, const __half* Al,
                                           const __half* Bh, const __half* Bl,
                                           int Kt, int m0, int n0) {
    int tid = threadIdx.x;
    int r = tid >> 1;                 // 0..127
    int c0 = (tid & 1) * 4;           // chunk 0..7 (16B each)
    uint32_t base = sb + s * STAGE;
    size_t rs = (size_t)Kt * 2;
    size_t kb = (size_t)ck * 128;
    const char* pA0 = (const char*)Ah + (size_t)(m0 + r) * rs + kb;
    const char* pA1 = (const char*)Al + (size_t)(m0 + r) * rs + kb;
    const char* pB0 = (const char*)Bh + (size_t)(n0 + r) * rs + kb;
    const char* pB1 = (const char*)Bl + (size_t)(n0 + r) * rs + kb;
#pragma unroll
    for (int c = 0; c < 4; c++) {
        int ch = c0 + c;
        uint32_t so = sw128((uint32_t)(r * 128 + ch * 16));
        CP16(base + so,         pA0 + ch * 16);
        CP16(base + 16384 + so, pA1 + ch * 16);
        CP16(base + 32768 + so, pB0 + ch * 16);
        CP16(base + 49152 + so, pB1 + ch * 16);
    }
    CP_COMMIT();
}

__device__ __forceinline__ void compute_chunk(uint32_t base, int lane, int wm, int wn,
                                              float acc[2][8][4]) {
#pragma unroll
    for (int k16 = 0; k16 < 4; k16++) {
        uint32_t koff = k16 * 32 + (lane >> 4) * 16;
        uint32_t ah[2][4], al[2][4];
#pragma unroll
        for (int mt = 0; mt < 2; mt++) {
            int row = wm * 32 + mt * 16 + (lane & 15);
            uint32_t off = sw128((uint32_t)(row * 128) + koff);
            LDSM4(ah[mt][0], ah[mt][1], ah[mt][2], ah[mt][3], base + off);
            LDSM4(al[mt][0], al[mt][1], al[mt][2], al[mt][3], base + 16384 + off);
        }
        uint32_t bh[8][2], bl[8][2];
#pragma unroll
        for (int g = 0; g < 4; g++) {
            int row = wn * 64 + g * 16 + (lane & 15);
            uint32_t off = sw128((uint32_t)(row * 128) + koff);
            uint32_t q0, q1, q2, q3;
            LDSM4(q0, q1, q2, q3, base + 32768 + off);
            bh[2 * g][0] = q0; bh[2 * g][1] = q2;
            bh[2 * g + 1][0] = q1; bh[2 * g + 1][1] = q3;
            LDSM4(q0, q1, q2, q3, base + 49152 + off);
            bl[2 * g][0] = q0; bl[2 * g][1] = q2;
            bl[2 * g + 1][0] = q1; bl[2 * g + 1][1] = q3;
        }
#pragma unroll
        for (int mt = 0; mt < 2; mt++)
#pragma unroll
            for (int nt = 0; nt < 8; nt++) {
                MMA(acc[mt][nt], ah[mt], bh[nt][0], bh[nt][1]);
                MMA(acc[mt][nt], ah[mt], bl[nt][0], bl[nt][1]);
                MMA(acc[mt][nt], al[mt], bh[nt][0], bh[nt][1]);
            }
    }
}

__device__ __forceinline__ void gemm_main(uint32_t sb,
                                          const __half* Ah, const __half* Al,
                                          const __half* Bh, const __half* Bl,
                                          int Kt, int m0, int n0, float acc[2][8][4]) {
#pragma unroll
    for (int i = 0; i < 2; i++)
#pragma unroll
        for (int j = 0; j < 8; j++)
#pragma unroll
            for (int q = 0; q < 4; q++) acc[i][j][q] = 0.f;

    const int NK = Kt >> 6;
    const int lane = threadIdx.x & 31, wid = threadIdx.x >> 5;
    const int wm = wid & 3, wn = wid >> 2;

    load_stage(sb, 0, 0, Ah, Al, Bh, Bl, Kt, m0, n0);
    for (int ck = 0; ck < NK; ck++) {
        if (ck + 1 < NK) {
            load_stage(sb, (ck + 1) & 1, ck + 1, Ah, Al, Bh, Bl, Kt, m0, n0);
            asm volatile("cp.async.wait_group 1;" ::: "memory");
        } else {
            asm volatile("cp.async.wait_group 0;" ::: "memory");
        }
        __syncthreads();
        compute_chunk(sb + (ck & 1) * STAGE, lane, wm, wn, acc);
        __syncthreads();
    }
}

// ---------------------------------------------------------------------------
// GEMM1: h[4096,2048] = y16[cur] @ w1t^T   (fp32 out to g_h)
__global__ __launch_bounds__(256, 1) void gemm1_mma(int cur, int stage) {
    extern __shared__ char smem[];
    uint32_t sb = smem_u32(smem);
    int m0 = blockIdx.y * 128, n0 = blockIdx.x * 128;
    float acc[2][8][4];
    gemm_main(sb, g_y16[cur][0], g_y16[cur][1],
              g_w1t[stage][0], g_w1t[stage][1], K1, m0, n0, acc);

    int lane = threadIdx.x & 31, wid = threadIdx.x >> 5;
    int wm = wid & 3, wn = wid >> 2;
#pragma unroll
    for (int mt = 0; mt < 2; mt++) {
        int r0 = m0 + wm * 32 + mt * 16 + (lane >> 2);
#pragma unroll
        for (int nt = 0; nt < 8; nt++) {
            int cc = n0 + wn * 64 + nt * 8 + (lane & 3) * 2;
            *(float2*)&g_h[(size_t)r0 * N1 + cc] =
                make_float2(acc[mt][nt][0], acc[mt][nt][1]);
            *(float2*)&g_h[(size_t)(r0 + 8) * N1 + cc] =
                make_float2(acc[mt][nt][2], acc[mt][nt][3]);
        }
    }
}

// ---------------------------------------------------------------------------
// GEMM2: cand = h2 @ w2t^T; epilogue: +b2, residual, Benes scatter, hi/lo split.
__global__ __launch_bounds__(256, 1) void gemm2_mma(int stage, int dir, int cur,
                                                    const float* __restrict__ b2,
                                                    float* __restrict__ dext) {
    extern __shared__ char smem[];
    uint32_t sb = smem_u32(smem);
    int m0 = blockIdx.y * 128, n0 = blockIdx.x * 128;
    float acc[2][8][4];
    gemm_main(sb, g_h2[0], g_h2[1],
              g_w2t[stage][0], g_w2t[stage][1], K2, m0, n0, acc);

    int lane = threadIdx.x & 31, wid = threadIdx.x >> 5;
    int wm = wid & 3, wn = wid >> 2;
    const __half* yh = g_y16[cur][0];
    const __half* yl = g_y16[cur][1];
    __half* oh = g_y16[cur ^ 1][0];
    __half* ol = g_y16[cur ^ 1][1];

#pragma unroll
    for (int mt = 0; mt < 2; mt++) {
        int rbase = m0 + wm * 32 + mt * 16 + (lane >> 2);
#pragma unroll
        for (int nt = 0; nt < 8; nt++) {
            int n = n0 + wn * 64 + nt * 8 + (lane & 3) * 2;
            int c = n & (NU - 1);
            int b = n >> 9;
            float2 bias = *(const float2*)&b2[n];
            float sig0 = g_sig[stage * NU + c];
            float sig1 = g_sig[stage * NU + c + 1];
#pragma unroll
            for (int hf = 0; hf < 2; hf++) {
                int r = rbase + hf * 8;
                int rowY = 2 * r + b;
                float cand0 = acc[mt][nt][hf * 2 + 0] + bias.x;
                float cand1 = acc[mt][nt][hf * 2 + 1] + bias.y;
                __half2 vh = *(const __half2*)&yh[(size_t)rowY * NU + c];
                __half2 vl = *(const __half2*)&yl[(size_t)rowY * NU + c];
                float v0 = sig0 * (__half2float(vh.x) + __half2float(vl.x)) + cand0 * CW_F;
                float v1 = sig1 * (__half2float(vh.y) + __half2float(vl.y)) + cand1 * CW_F;
                int dst;
                if (dir == 0)      dst = (rowY < M_) ? (2 * rowY) : (2 * rowY - L + 1);
                else if (dir == 1) dst = (rowY & 1) ? (M_ + (rowY >> 1)) : (rowY >> 1);
                else               dst = rowY;
                if (dext) {
                    *(float2*)&dext[(size_t)dst * NU + c] = make_float2(v0, v1);
                } else {
                    __half h0, l0, h1, l1;
                    split_h(v0, h0, l0);
                    split_h(v1, h1, l1);
                    *(__half2*)&oh[(size_t)dst * NU + c] = __halves2half2(h0, h1);
                    *(__half2*)&ol[(size_t)dst * NU + c] = __halves2half2(l0, l1);
                }
            }
        }
    }
}

// ---------------------------------------------------------------------------
extern "C" void kernel_launch(void* const* d_in, const int* in_sizes, int n_in,
                              void* d_out, int out_size) {
    const float* x = (const float*)d_in[0];
    const float* rs[3] = {(const float*)d_in[1], (const float*)d_in[5], (const float*)d_in[9]};
    const float* w1[3] = {(const float*)d_in[2], (const float*)d_in[6], (const float*)d_in[10]};
    const float* w2[3] = {(const float*)d_in[3], (const float*)d_in[7], (const float*)d_in[11]};
    const float* b2[3] = {(const float*)d_in[4], (const float*)d_in[8], (const float*)d_in[12]};
    float* out = (float*)d_out;

    cudaFuncSetAttribute(gemm1_mma, cudaFuncAttributeMaxDynamicSharedMemorySize, SMEM_DYN);
    cudaFuncSetAttribute(gemm2_mma, cudaFuncAttributeMaxDynamicSharedMemorySize, SMEM_DYN);

    copy_x_split_kernel<<<(L * NU + 255) / 256, 256>>>(x);
    sig_kernel<<<6, 256>>>(rs[0], rs[1], rs[2]);
    for (int s = 0; s < 3; s++) {
        transpose_split_kernel<<<dim3(N1 / 32, K1 / 32), dim3(32, 8)>>>(w1[s], K1, N1, 0, s);
        transpose_split_kernel<<<dim3(N2 / 32, K2 / 32), dim3(32, 8)>>>(w2[s], K2, N2, 1, s);
    }

    dim3 g1(N1 / 128, M_ / 128);   // (16, 32)
    dim3 g2(N2 / 128, M_ / 128);   // (8, 32)

    int cur = 0;
    for (int step = 0; step < 25; step++) {
        int stage = (step < 12) ? 0 : (step < 24) ? 1 : 2;
        int dir = stage;
        gemm1_mma<<<g1, 256, SMEM_DYN>>>(cur, stage);
        stats_partial_kernel<<<dim3(64, 8), dim3(32, 8)>>>();
        stats_final_kernel<<<8, 256>>>();
        prep2_kernel<<<M_ * N1 / 1024, 256>>>();
        gemm2_mma<<<g2, 256, SMEM_DYN>>>(stage, dir, cur, b2[stage],
                                         (step == 24) ? out : nullptr);
        cur ^= 1;
    }
}